// round 12
// baseline (speedup 1.0000x reference)
#include <cuda_runtime.h>
#include <cuda_bf16.h>

// FHN IMEX dynamics, (4,4096,2048) fp32, 8 steps.
// Persistent CTAs (152x5), register prefetch of next row's stimulus.
// One row = 2048 elems = 256 threads x 8 elems (two float4).
// Scale-independent conditioning (MUFU-heavy) computed BEFORE the row barrier
// so it executes in the barrier shadow (BAR defer-blocks at the smem read).
// s = P - dt*w folding; fast path (dt==1,...) with exact step elisions.

#define FHN_TAU 12.5f
#define L2E 1.4426950408889634f

typedef unsigned long long ull;

union UF { ull u; float2 f; };

__device__ __forceinline__ ull pk2(float lo, float hi) {
    UF r; r.f.x = lo; r.f.y = hi; return r.u;
}
__device__ __forceinline__ ull fma2(ull a, ull b, ull c) {
    ull d; asm("fma.rn.f32x2 %0, %1, %2, %3;" : "=l"(d) : "l"(a), "l"(b), "l"(c)); return d;
}
__device__ __forceinline__ ull mul2(ull a, ull b) {
    ull d; asm("mul.rn.f32x2 %0, %1, %2;" : "=l"(d) : "l"(a), "l"(b)); return d;
}
__device__ __forceinline__ ull clip2(ull x) {
    UF v; v.u = x;
    v.f.x = fminf(fmaxf(v.f.x, -3.0f), 3.0f);
    v.f.y = fminf(fmaxf(v.f.y, -3.0f), 3.0f);
    return v.u;
}
// q = x * (0.1 + 0.9 * sigmoid((|x|-0.5)*10))
__device__ __forceinline__ float cond_q(float xv) {
    float e = exp2f(fmaf(-10.0f * L2E, fabsf(xv), 5.0f * L2E));
    float g = __fdividef(1.0f, 1.0f + e);
    return xv * fmaf(0.9f, g, 0.1f);
}

__global__ __launch_bounds__(256, 5)
void fhn_kernel(const float* __restrict__ stim,
                const float* __restrict__ a_p,
                const float* __restrict__ b_p,
                const float* __restrict__ dt_p,
                const int*   __restrict__ ns_p,
                float* __restrict__ out,
                long long N, int rows, int writeV)
{
    const int t = threadIdx.x;

    // ---- hoisted scalars / per-step constants (once per CTA) ----
    const float a  = *a_p;
    const float b  = *b_p;
    const float dt = *dt_p;
    const int   n_steps = ns_p ? *ns_p : 8;

    const float alpha = dt / FHN_TAU;
    const float denom = 1.0f + alpha * b;
    const float k1 = 1.0f / denom;
    const float k2 = alpha / denom;
    const float k3 = alpha * a / denom;
    const float c1 = 1.0f + dt;              // v_pre = v*(c1 - c3*v^2) + s
    const float c3 = dt * (1.0f / 3.0f);
    const float omk1 = 1.0f - k1;            // s' = k1*s + nck*v_pre + P2
    const float ndk3 = -dt * k3;
    const float nck  = -dt * k2;

    const ull C1   = pk2(c1, c1);
    const ull NC3  = pk2(-c3, -c3);
    const ull K1   = pk2(k1, k1);
    const ull NCK  = pk2(nck, nck);
    const ull OMK1 = pk2(omk1, omk1);
    const ull NDK3 = pk2(ndk3, ndk3);

    const bool fast8 = (n_steps == 8) && (dt == 1.0f) &&
                       (fabsf(a) <= 1.0f) && (b >= 0.0f);

    __shared__ float wmax[2][8];

    // ---- prefetch first row ----
    int row = blockIdx.x;
    const int stride = gridDim.x;

    const float4* s4 = reinterpret_cast<const float4*>(stim) + (long long)row * 512;
    float4 x0 = __ldcs(s4 + t);
    float4 x1 = __ldcs(s4 + t + 256);

    int buf = 0;
    for (; row < rows; row += stride, buf ^= 1) {
        // ---- prefetch next row (latency hidden behind this row's compute) ----
        float4 nx0, nx1;
        const int nrow = row + stride;
        if (nrow < rows) {
            const float4* n4 = reinterpret_cast<const float4*>(stim) + (long long)nrow * 512;
            nx0 = __ldcs(n4 + t);
            nx1 = __ldcs(n4 + t + 256);
        }

        // ---- row max(|x|): warp redux + smem write (before conditioning) ----
        float m = fmaxf(fmaxf(fmaxf(fabsf(x0.x), fabsf(x0.y)), fmaxf(fabsf(x0.z), fabsf(x0.w))),
                        fmaxf(fmaxf(fabsf(x1.x), fabsf(x1.y)), fmaxf(fabsf(x1.z), fabsf(x1.w))));
        m = __uint_as_float(__reduce_max_sync(0xffffffffu, __float_as_uint(m)));
        if ((t & 31) == 0) wmax[buf][t >> 5] = m;

        // ---- scale-independent conditioning IN THE BARRIER SHADOW ----
        // q = x*(0.1+0.9*sigmoid(10(|x|-0.5)));  P = (dt/scale)*q (after barrier)
        ull Q[4];
        Q[0] = pk2(cond_q(x0.x), cond_q(x0.y));
        Q[1] = pk2(cond_q(x0.z), cond_q(x0.w));
        Q[2] = pk2(cond_q(x1.x), cond_q(x1.y));
        Q[3] = pk2(cond_q(x1.z), cond_q(x1.w));

        __syncthreads();   // defer-blocks at the wmax read below

        m = wmax[buf][0];
        #pragma unroll
        for (int i = 1; i < 8; ++i) m = fmaxf(m, wmax[buf][i]);

        const float scale = fmaxf(m, 1e-6f);
        const float di = dt * __fdividef(1.0f, scale);
        const ull  DI = pk2(di, di);

        ull P2[4], V[4], S[4];
        #pragma unroll
        for (int j = 0; j < 4; ++j) {
            S[j]  = mul2(DI, Q[j]);              // s0 = P (w0 = 0)
            P2[j] = fma2(OMK1, S[j], NDK3);      // P2 = (1-k1)*P - dt*k3
            V[j]  = 0ull;
        }

#define FHN_STEP(j)                                             \
    do {                                                        \
        ull T  = mul2(V[j], V[j]);                              \
        ull R  = fma2(NC3, T, C1);                              \
        ull Vp = fma2(R, V[j], S[j]);                           \
        S[j]   = fma2(K1, S[j], fma2(NCK, Vp, P2[j]));          \
        V[j]   = clip2(Vp);                                     \
    } while (0)

#define FHN_STEP_NOCLIP(j)                                      \
    do {                                                        \
        ull T  = mul2(V[j], V[j]);                              \
        ull R  = fma2(NC3, T, C1);                              \
        ull Vp = fma2(R, V[j], S[j]);                           \
        S[j]   = fma2(K1, S[j], fma2(NCK, Vp, P2[j]));          \
        V[j]   = Vp;                                            \
    } while (0)

#define FHN_STEP_LAST(j)                                        \
    do {                                                        \
        ull T  = mul2(V[j], V[j]);                              \
        ull R  = fma2(NC3, T, C1);                              \
        ull Vp = fma2(R, V[j], S[j]);                           \
        V[j]   = clip2(Vp);                                     \
    } while (0)

        if (fast8) {
            // step 1 folded: v_pre1 = S0 exactly (V=0); clip identity (|P|<=1)
            #pragma unroll
            for (int j = 0; j < 4; ++j) {
                ull S0 = S[j];
                V[j] = S0;
                S[j] = fma2(K1, S0, fma2(NCK, S0, P2[j]));
            }
            // step 2: clip provably inactive (|v_pre2| <= 2.83 < 3)
            FHN_STEP_NOCLIP(0); FHN_STEP_NOCLIP(1); FHN_STEP_NOCLIP(2); FHN_STEP_NOCLIP(3);
            // steps 3..7: full
            #pragma unroll
            for (int s = 0; s < 5; ++s) {
                FHN_STEP(0); FHN_STEP(1); FHN_STEP(2); FHN_STEP(3);
            }
            // step 8: S-update dead
            FHN_STEP_LAST(0); FHN_STEP_LAST(1); FHN_STEP_LAST(2); FHN_STEP_LAST(3);
        } else if (n_steps == 8) {
            #pragma unroll
            for (int s = 0; s < 8; ++s) {
                FHN_STEP(0); FHN_STEP(1); FHN_STEP(2); FHN_STEP(3);
            }
        } else {
            for (int s = 0; s < n_steps; ++s) {
                FHN_STEP(0); FHN_STEP(1); FHN_STEP(2); FHN_STEP(3);
            }
        }
#undef FHN_STEP
#undef FHN_STEP_NOCLIP
#undef FHN_STEP_LAST

        // ---- outputs: response = v*scale at [0,N), v at [N,2N) (streaming) ----
        const ull SC = pk2(scale, scale);
        UF v0, v1, v2, v3, r0, r1, r2, r3;
        v0.u = V[0]; v1.u = V[1]; v2.u = V[2]; v3.u = V[3];
        r0.u = mul2(V[0], SC); r1.u = mul2(V[1], SC);
        r2.u = mul2(V[2], SC); r3.u = mul2(V[3], SC);

        const long long base = (long long)row * 2048;
        float4* o4 = reinterpret_cast<float4*>(out + base);
        __stcs(o4 + t,       make_float4(r0.f.x, r0.f.y, r1.f.x, r1.f.y));
        __stcs(o4 + t + 256, make_float4(r2.f.x, r2.f.y, r3.f.x, r3.f.y));

        if (writeV) {
            float4* v4 = reinterpret_cast<float4*>(out + N + base);
            __stcs(v4 + t,       make_float4(v0.f.x, v0.f.y, v1.f.x, v1.f.y));
            __stcs(v4 + t + 256, make_float4(v2.f.x, v2.f.y, v3.f.x, v3.f.y));
        }

        // rotate prefetch buffers
        x0 = nx0; x1 = nx1;
    }
}

extern "C" void kernel_launch(void* const* d_in, const int* in_sizes, int n_in,
                              void* d_out, int out_size)
{
    const float* stim = (const float*)d_in[0];
    const float* a    = (const float*)d_in[1];
    const float* b    = (const float*)d_in[2];
    const float* dt   = (const float*)d_in[3];
    const int*   ns   = (n_in > 4) ? (const int*)d_in[4] : nullptr;

    long long N = (long long)in_sizes[0];          // 33,554,432
    int rows = (int)(N / 2048);                    // 16384 rows
    int writeV = ((long long)out_size >= 2 * N) ? 1 : 0;

    int grid = 152 * 5;                            // persistent: SMs x CTAs/SM
    if (grid > rows) grid = rows;

    fhn_kernel<<<grid, 256>>>(stim, a, b, dt, ns, (float*)d_out, N, rows, writeV);
}

// round 13
// speedup vs baseline: 1.0310x; 1.0310x over previous
#include <cuda_runtime.h>
#include <cuda_bf16.h>

// FHN IMEX dynamics, (4,4096,2048) fp32, 8 steps.
// Persistent CTAs (152x5), register prefetch of next row's stimulus.
// One row = 2048 elems = 256 threads x 8 contiguous elems (one 256-bit ld/st).
// Blackwell 256-bit global ld/st (v8.f32) halves memory instruction count.
// s = P - dt*w folding; fast path (dt==1,...) with exact step elisions.

#define FHN_TAU 12.5f
#define L2E 1.4426950408889634f

typedef unsigned long long ull;

union UF { ull u; float2 f; };

__device__ __forceinline__ ull pk2(float lo, float hi) {
    UF r; r.f.x = lo; r.f.y = hi; return r.u;
}
__device__ __forceinline__ ull fma2(ull a, ull b, ull c) {
    ull d; asm("fma.rn.f32x2 %0, %1, %2, %3;" : "=l"(d) : "l"(a), "l"(b), "l"(c)); return d;
}
__device__ __forceinline__ ull mul2(ull a, ull b) {
    ull d; asm("mul.rn.f32x2 %0, %1, %2;" : "=l"(d) : "l"(a), "l"(b)); return d;
}
__device__ __forceinline__ ull clip2(ull x) {
    UF v; v.u = x;
    v.f.x = fminf(fmaxf(v.f.x, -3.0f), 3.0f);
    v.f.y = fminf(fmaxf(v.f.y, -3.0f), 3.0f);
    return v.u;
}
// q = x * (0.1 + 0.9 * sigmoid((|x|-0.5)*10))
__device__ __forceinline__ float cond_q(float xv) {
    float e = exp2f(fmaf(-10.0f * L2E, fabsf(xv), 5.0f * L2E));
    float g = __fdividef(1.0f, 1.0f + e);
    return xv * fmaf(0.9f, g, 0.1f);
}

// ---- Blackwell 256-bit global load/store (sm_100+) ----
__device__ __forceinline__ void ldg256_cs(const float* p, float4& lo, float4& hi) {
    asm("ld.global.cs.v8.f32 {%0,%1,%2,%3,%4,%5,%6,%7}, [%8];"
        : "=f"(lo.x), "=f"(lo.y), "=f"(lo.z), "=f"(lo.w),
          "=f"(hi.x), "=f"(hi.y), "=f"(hi.z), "=f"(hi.w)
        : "l"(p));
}
__device__ __forceinline__ void stg256_cs(float* p, float4 lo, float4 hi) {
    asm volatile("st.global.cs.v8.f32 [%0], {%1,%2,%3,%4,%5,%6,%7,%8};"
        :: "l"(p),
           "f"(lo.x), "f"(lo.y), "f"(lo.z), "f"(lo.w),
           "f"(hi.x), "f"(hi.y), "f"(hi.z), "f"(hi.w)
        : "memory");
}

__global__ __launch_bounds__(256, 5)
void fhn_kernel(const float* __restrict__ stim,
                const float* __restrict__ a_p,
                const float* __restrict__ b_p,
                const float* __restrict__ dt_p,
                const int*   __restrict__ ns_p,
                float* __restrict__ out,
                long long N, int rows, int writeV)
{
    const int t = threadIdx.x;

    // ---- hoisted scalars / per-step constants (once per CTA) ----
    const float a  = *a_p;
    const float b  = *b_p;
    const float dt = *dt_p;
    const int   n_steps = ns_p ? *ns_p : 8;

    const float alpha = dt / FHN_TAU;
    const float denom = 1.0f + alpha * b;
    const float k1 = 1.0f / denom;
    const float k2 = alpha / denom;
    const float k3 = alpha * a / denom;
    const float c1 = 1.0f + dt;              // v_pre = v*(c1 - c3*v^2) + s
    const float c3 = dt * (1.0f / 3.0f);
    const float omk1 = 1.0f - k1;            // s' = k1*s + nck*v_pre + P2
    const float ndk3 = -dt * k3;
    const float nck  = -dt * k2;

    const ull C1   = pk2(c1, c1);
    const ull NC3  = pk2(-c3, -c3);
    const ull K1   = pk2(k1, k1);
    const ull NCK  = pk2(nck, nck);
    const ull OMK1 = pk2(omk1, omk1);
    const ull NDK3 = pk2(ndk3, ndk3);

    const bool fast8 = (n_steps == 8) && (dt == 1.0f) &&
                       (fabsf(a) <= 1.0f) && (b >= 0.0f);

    __shared__ float wmax[2][8];

    // ---- prefetch first row: one 256-bit load (elements 8t..8t+7) ----
    int row = blockIdx.x;
    const int stride = gridDim.x;

    float4 x0, x1;
    ldg256_cs(stim + (long long)row * 2048 + t * 8, x0, x1);

    int buf = 0;
    for (; row < rows; row += stride, buf ^= 1) {
        // ---- prefetch next row (latency hidden behind this row's compute) ----
        float4 nx0, nx1;
        const int nrow = row + stride;
        if (nrow < rows) {
            ldg256_cs(stim + (long long)nrow * 2048 + t * 8, nx0, nx1);
        }

        // ---- row max(|x|): warp redux + smem write ----
        float m = fmaxf(fmaxf(fmaxf(fabsf(x0.x), fabsf(x0.y)), fmaxf(fabsf(x0.z), fabsf(x0.w))),
                        fmaxf(fmaxf(fabsf(x1.x), fabsf(x1.y)), fmaxf(fabsf(x1.z), fabsf(x1.w))));
        m = __uint_as_float(__reduce_max_sync(0xffffffffu, __float_as_uint(m)));
        if ((t & 31) == 0) wmax[buf][t >> 5] = m;

        // ---- scale-independent conditioning in the barrier shadow ----
        ull Q[4];
        Q[0] = pk2(cond_q(x0.x), cond_q(x0.y));
        Q[1] = pk2(cond_q(x0.z), cond_q(x0.w));
        Q[2] = pk2(cond_q(x1.x), cond_q(x1.y));
        Q[3] = pk2(cond_q(x1.z), cond_q(x1.w));

        __syncthreads();   // defer-blocks at the wmax read below

        m = wmax[buf][0];
        #pragma unroll
        for (int i = 1; i < 8; ++i) m = fmaxf(m, wmax[buf][i]);

        const float scale = fmaxf(m, 1e-6f);
        const float di = dt * __fdividef(1.0f, scale);
        const ull  DI = pk2(di, di);

        ull P2[4], V[4], S[4];
        #pragma unroll
        for (int j = 0; j < 4; ++j) {
            S[j]  = mul2(DI, Q[j]);              // s0 = P (w0 = 0)
            P2[j] = fma2(OMK1, S[j], NDK3);      // P2 = (1-k1)*P - dt*k3
            V[j]  = 0ull;
        }

#define FHN_STEP(j)                                             \
    do {                                                        \
        ull T  = mul2(V[j], V[j]);                              \
        ull R  = fma2(NC3, T, C1);                              \
        ull Vp = fma2(R, V[j], S[j]);                           \
        S[j]   = fma2(K1, S[j], fma2(NCK, Vp, P2[j]));          \
        V[j]   = clip2(Vp);                                     \
    } while (0)

#define FHN_STEP_NOCLIP(j)                                      \
    do {                                                        \
        ull T  = mul2(V[j], V[j]);                              \
        ull R  = fma2(NC3, T, C1);                              \
        ull Vp = fma2(R, V[j], S[j]);                           \
        S[j]   = fma2(K1, S[j], fma2(NCK, Vp, P2[j]));          \
        V[j]   = Vp;                                            \
    } while (0)

#define FHN_STEP_LAST(j)                                        \
    do {                                                        \
        ull T  = mul2(V[j], V[j]);                              \
        ull R  = fma2(NC3, T, C1);                              \
        ull Vp = fma2(R, V[j], S[j]);                           \
        V[j]   = clip2(Vp);                                     \
    } while (0)

        if (fast8) {
            // step 1 folded: v_pre1 = S0 exactly (V=0); clip identity (|P|<=1)
            #pragma unroll
            for (int j = 0; j < 4; ++j) {
                ull S0 = S[j];
                V[j] = S0;
                S[j] = fma2(K1, S0, fma2(NCK, S0, P2[j]));
            }
            // step 2: clip provably inactive (|v_pre2| <= 2.83 < 3)
            FHN_STEP_NOCLIP(0); FHN_STEP_NOCLIP(1); FHN_STEP_NOCLIP(2); FHN_STEP_NOCLIP(3);
            // steps 3..7: full
            #pragma unroll
            for (int s = 0; s < 5; ++s) {
                FHN_STEP(0); FHN_STEP(1); FHN_STEP(2); FHN_STEP(3);
            }
            // step 8: S-update dead
            FHN_STEP_LAST(0); FHN_STEP_LAST(1); FHN_STEP_LAST(2); FHN_STEP_LAST(3);
        } else if (n_steps == 8) {
            #pragma unroll
            for (int s = 0; s < 8; ++s) {
                FHN_STEP(0); FHN_STEP(1); FHN_STEP(2); FHN_STEP(3);
            }
        } else {
            for (int s = 0; s < n_steps; ++s) {
                FHN_STEP(0); FHN_STEP(1); FHN_STEP(2); FHN_STEP(3);
            }
        }
#undef FHN_STEP
#undef FHN_STEP_NOCLIP
#undef FHN_STEP_LAST

        // ---- outputs: response = v*scale at [0,N), v at [N,2N) ----
        const ull SC = pk2(scale, scale);
        UF v0, v1, v2, v3, r0, r1, r2, r3;
        v0.u = V[0]; v1.u = V[1]; v2.u = V[2]; v3.u = V[3];
        r0.u = mul2(V[0], SC); r1.u = mul2(V[1], SC);
        r2.u = mul2(V[2], SC); r3.u = mul2(V[3], SC);

        const long long base = (long long)row * 2048 + t * 8;
        stg256_cs(out + base,
                  make_float4(r0.f.x, r0.f.y, r1.f.x, r1.f.y),
                  make_float4(r2.f.x, r2.f.y, r3.f.x, r3.f.y));

        if (writeV) {
            stg256_cs(out + N + base,
                      make_float4(v0.f.x, v0.f.y, v1.f.x, v1.f.y),
                      make_float4(v2.f.x, v2.f.y, v3.f.x, v3.f.y));
        }

        // rotate prefetch buffers
        x0 = nx0; x1 = nx1;
    }
}

extern "C" void kernel_launch(void* const* d_in, const int* in_sizes, int n_in,
                              void* d_out, int out_size)
{
    const float* stim = (const float*)d_in[0];
    const float* a    = (const float*)d_in[1];
    const float* b    = (const float*)d_in[2];
    const float* dt   = (const float*)d_in[3];
    const int*   ns   = (n_in > 4) ? (const int*)d_in[4] : nullptr;

    long long N = (long long)in_sizes[0];          // 33,554,432
    int rows = (int)(N / 2048);                    // 16384 rows
    int writeV = ((long long)out_size >= 2 * N) ? 1 : 0;

    int grid = 152 * 5;                            // persistent: SMs x CTAs/SM
    if (grid > rows) grid = rows;

    fhn_kernel<<<grid, 256>>>(stim, a, b, dt, ns, (float*)d_out, N, rows, writeV);
}